// round 8
// baseline (speedup 1.0000x reference)
#include <cuda_runtime.h>

#define NN 100000
#define EE 900000
#define IND 128
#define HIDD 64
#define NB_SCAN 98   // ceil(100000/1024)

// ---------------- scratch (static device globals; no allocations) -------------
__device__ float  g_X [NN * HIDD];
__device__ float  g_Ya[NN * HIDD];
__device__ float  g_Yb[NN * HIDD];
__device__ float  g_nrm[NN];       // per-node 1/sqrt(dt) (for edge coefs)
__device__ float2 g_nd [NN];       // packed {nrm, dtinv} for prop epilogue
__device__ int2   g_ec[EE];        // per-CSR-edge packed {src, coef_bits}
__device__ float  g_wc[EE];        // attention weights, CSR order
__device__ int    g_rowptr[NN + 1];
__device__ int    g_cnt[NN];
__device__ volatile int g_bflag[NB_SCAN];
__device__ int    g_bval[NB_SCAN];
__device__ int    g_bagg[NB_SCAN];

__device__ __forceinline__ float* selbuf(int s) {
    return s == 0 ? g_X : (s == 1 ? g_Ya : g_Yb);
}

// ---------------- CSR build ---------------------------------------------------
__global__ void k_zero_cnt() {
    int i = blockIdx.x * blockDim.x + threadIdx.x;
    if (i < NN) g_cnt[i] = 0;
    if (i < NB_SCAN) g_bflag[i] = 0;
}

__global__ void k_count(const int* __restrict__ dst, int E) {
    int q = blockIdx.x * blockDim.x + threadIdx.x;
    int base = q * 4;
    if (base + 4 <= E) {
        int4 d = *(const int4*)(dst + base);
        atomicAdd(&g_cnt[d.x], 1);
        atomicAdd(&g_cnt[d.y], 1);
        atomicAdd(&g_cnt[d.z], 1);
        atomicAdd(&g_cnt[d.w], 1);
    } else {
        for (int e = base; e < E; ++e) atomicAdd(&g_cnt[dst[e]], 1);
    }
}

// Single-pass scan (decoupled lookback) + cursor init + phase-1 node coefs.
__global__ void k_scanF() {
    __shared__ int s[1024];
    __shared__ int s_ex;
    int bid = blockIdx.x;
    int tid = threadIdx.x;
    int i = bid * 1024 + tid;
    int cntv = (i < NN) ? g_cnt[i] : 0;
    s[tid] = cntv;
    __syncthreads();
    for (int off = 1; off < 1024; off <<= 1) {
        int t = (tid >= off) ? s[tid - off] : 0;
        __syncthreads();
        s[tid] += t;
        __syncthreads();
    }
    int inc = s[tid];
    int agg = s[1023];

    if (tid == 0) {
        if (bid == 0) {
            g_bval[0] = agg;
            __threadfence();
            g_bflag[0] = 2;
            s_ex = 0;
        } else {
            g_bagg[bid] = agg;
            __threadfence();
            g_bflag[bid] = 1;
        }
    }
    if (bid > 0 && tid < 32) {
        int lane = tid;
        int ex = 0;
        int j = bid - 1;
        while (true) {
            int jj = j - lane;
            int f = 2, v = 0;
            if (jj >= 0) {
                while ((f = g_bflag[jj]) == 0) { }
                __threadfence();
                v = (f == 2) ? g_bval[jj] : g_bagg[jj];
            }
            unsigned ball = __ballot_sync(0xffffffffu, f == 2);
            if (ball) {
                int firstP = __ffs(ball) - 1;
                int contrib = (lane <= firstP) ? v : 0;
                #pragma unroll
                for (int o = 16; o > 0; o >>= 1) contrib += __shfl_xor_sync(0xffffffffu, contrib, o);
                ex += contrib;
                break;
            } else {
                #pragma unroll
                for (int o = 16; o > 0; o >>= 1) v += __shfl_xor_sync(0xffffffffu, v, o);
                ex += v;
                j -= 32;
            }
        }
        if (lane == 0) {
            s_ex = ex;
            g_bval[bid] = ex + agg;
            __threadfence();
            g_bflag[bid] = 2;
        }
    }
    __syncthreads();
    int ex = s_ex;
    if (i < NN) {
        int incl = ex + inc;
        g_rowptr[i + 1] = incl;
        g_cnt[i] = incl - cntv;         // cursor = exclusive prefix
        float d = (float)cntv;           // in-degree (>=1, self loops)
        float nr = rsqrtf(d);
        g_nrm[i] = nr;
        g_nd[i]  = make_float2(nr, 1.0f / d);
    }
    if (i == 0) g_rowptr[0] = 0;
}

__global__ void k_scatter(const int* __restrict__ src, const int* __restrict__ dst, int E) {
    int e = blockIdx.x * blockDim.x + threadIdx.x;
    if (e < E) {
        int sv = src[e];
        int p = atomicAdd(&g_cnt[dst[e]], 1);
        g_ec[p] = make_int2(sv, __float_as_int(g_nrm[sv]));   // phase-1 coef
    }
}

// ---------------- phase-2 edge coefficients (2 edges/thread) --------------------
__global__ void k_coef2(int E) {
    int q = blockIdx.x * blockDim.x + threadIdx.x;
    int p = q * 2;
    if (p + 2 <= E) {
        int4 e2 = *(const int4*)&g_ec[p];
        float2 w2 = *(const float2*)&g_wc[p];
        e2.y = __float_as_int(w2.x * g_nrm[e2.x]);
        e2.w = __float_as_int(w2.y * g_nrm[e2.z]);
        *(int4*)&g_ec[p] = e2;
    } else if (p < E) {
        int2 e = g_ec[p];
        g_ec[p] = make_int2(e.x, __float_as_int(g_wc[p] * g_nrm[e.x]));
    }
}

// ---------------- propagation (warp per node, fp32, x2 loop; champion) ----------
__global__ void k_prop(int is, int os) {
    int gw   = (blockIdx.x * blockDim.x + threadIdx.x) >> 5;
    int lane = threadIdx.x & 31;
    if (gw >= NN) return;
    const float2* __restrict__ Yin  = (const float2*)selbuf(is);
    float2*       __restrict__ Yout = (float2*)selbuf(os);
    const float2* __restrict__ X2   = (const float2*)g_X;

    int beg = g_rowptr[gw], end = g_rowptr[gw + 1];
    float ax = 0.f, ay = 0.f;
    int p = beg;
    for (; p + 2 <= end; p += 2) {
        int2 e0 = g_ec[p];
        int2 e1 = g_ec[p + 1];
        float2 y0 = __ldcg(&Yin[e0.x * 32 + lane]);
        float2 y1 = __ldcg(&Yin[e1.x * 32 + lane]);
        float c0 = __int_as_float(e0.y);
        float c1 = __int_as_float(e1.y);
        ax = fmaf(c0, y0.x, ax); ay = fmaf(c0, y0.y, ay);
        ax = fmaf(c1, y1.x, ax); ay = fmaf(c1, y1.y, ay);
    }
    if (p < end) {
        int2 e0 = g_ec[p];
        float2 y0 = __ldcg(&Yin[e0.x * 32 + lane]);
        float c0 = __int_as_float(e0.y);
        ax = fmaf(c0, y0.x, ax); ay = fmaf(c0, y0.y, ay);
    }
    float2 nd = g_nd[gw];
    float nr = 0.5f * nd.x;
    float di = 0.5f * nd.y;
    float2 yv = Yin[gw * 32 + lane];
    float2 xv = X2 [gw * 32 + lane];
    float2 o;
    o.x = 0.5f * yv.x + nr * ax + di * xv.x;
    o.y = 0.5f * yv.y + nr * ay + di * xv.y;
    Yout[gw * 32 + lane] = o;
}

// ---------------- attention (warp per node, unroll x2) + fused node coefs -------
__global__ void k_attn(int is) {
    int gw   = (blockIdx.x * blockDim.x + threadIdx.x) >> 5;
    int lane = threadIdx.x & 31;
    if (gw >= NN) return;
    const float2* __restrict__ Y = (const float2*)selbuf(is);
    float2 hv = Y[gw * 32 + lane];
    int beg = g_rowptr[gw], end = g_rowptr[gw + 1];
    float dsum = 0.f;
    int p = beg;
    for (; p + 2 <= end; p += 2) {
        int s0 = g_ec[p].x;
        int s1 = g_ec[p + 1].x;
        float2 h0 = __ldcg(&Y[s0 * 32 + lane]);
        float2 h1 = __ldcg(&Y[s1 * 32 + lane]);
        float dx0 = h0.x - hv.x, dy0 = h0.y - hv.y;
        float dx1 = h1.x - hv.x, dy1 = h1.y - hv.y;
        float d0 = dx0 * dx0 + dy0 * dy0;
        float d1 = dx1 * dx1 + dy1 * dy1;
        #pragma unroll
        for (int o = 16; o > 0; o >>= 1) {
            d0 += __shfl_xor_sync(0xffffffffu, d0, o);
            d1 += __shfl_xor_sync(0xffffffffu, d1, o);
        }
        float w0 = sqrtf(fmaxf(d0, 0.f) + 1e-7f);
        float w1 = sqrtf(fmaxf(d1, 0.f) + 1e-7f);
        w0 = fmaxf(w0, 0.2f);
        w1 = fmaxf(w1, 0.2f);
        w0 = 1.0f / w0 + 1e-9f;
        w1 = 1.0f / w1 + 1e-9f;
        if (lane == 0) { g_wc[p] = w0; g_wc[p + 1] = w1; }
        dsum += w0 + w1;
    }
    if (p < end) {
        int s0 = g_ec[p].x;
        float2 h0 = __ldcg(&Y[s0 * 32 + lane]);
        float dx0 = h0.x - hv.x, dy0 = h0.y - hv.y;
        float d0 = dx0 * dx0 + dy0 * dy0;
        #pragma unroll
        for (int o = 16; o > 0; o >>= 1) d0 += __shfl_xor_sync(0xffffffffu, d0, o);
        float w0 = sqrtf(fmaxf(d0, 0.f) + 1e-7f);
        w0 = fmaxf(w0, 0.2f);
        w0 = 1.0f / w0 + 1e-9f;
        if (lane == 0) g_wc[p] = w0;
        dsum += w0;
    }
    if (lane == 0) {
        g_nrm[gw] = rsqrtf(dsum);
        g_nd[gw]  = make_float2(rsqrtf(dsum), 1.0f / dsum);
    }
}

// ---------------- tf32 tensor-core GEMM (3xTF32, fp32-accurate) -----------------
__device__ __forceinline__ unsigned f2tf(float x) {
    unsigned r;
    asm("cvt.rna.tf32.f32 %0, %1;" : "=r"(r) : "f"(x));
    return r;
}
__device__ __forceinline__ void mma_tf32(float d[4], unsigned a0, unsigned a1,
                                         unsigned a2, unsigned a3,
                                         unsigned b0, unsigned b1) {
    asm("mma.sync.aligned.m16n8k8.row.col.f32.tf32.tf32.f32 "
        "{%0,%1,%2,%3}, {%4,%5,%6,%7}, {%8,%9}, {%0,%1,%2,%3};"
        : "+f"(d[0]), "+f"(d[1]), "+f"(d[2]), "+f"(d[3])
        : "r"(a0), "r"(a1), "r"(a2), "r"(a3), "r"(b0), "r"(b1));
}

// C[nrows,64] = act(A[nrows,K]) @ W[K,64] + b ; block = 128 rows, 8 warps.
template <int K, bool RELU>
__global__ void k_gemm_tc(const float* __restrict__ Ain, const float* __restrict__ W,
                          const float* __restrict__ bias, float* __restrict__ Cout,
                          int nrows, int asel, int csel) {
    const float* A = Ain  ? Ain  : selbuf(asel);
    float*       C = Cout ? Cout : selbuf(csel);

    __shared__ float sW[K][65];
    __shared__ float sA[128][33];

    int tid  = threadIdx.x;
    int wid  = tid >> 5;
    int lane = tid & 31;
    int rg   = lane >> 2;    // row group 0..7
    int cg   = lane & 3;     // col group 0..3
    int row0 = blockIdx.x * 128;
    int m0   = wid * 16;

    // load W [K,64] into smem (coalesced)
    for (int i = tid; i < K * 64; i += 256) sW[i >> 6][i & 63] = W[i];

    float d[8][4];
    #pragma unroll
    for (int nt = 0; nt < 8; ++nt)
        #pragma unroll
        for (int j = 0; j < 4; ++j) d[nt][j] = 0.f;

    for (int kc = 0; kc < K; kc += 32) {
        __syncthreads();
        // stage A chunk: 128 rows x 32 k
        for (int i = tid; i < 128 * 8; i += 256) {
            int r = i >> 3, q = i & 7;
            int row = row0 + r;
            float4 a = make_float4(0.f, 0.f, 0.f, 0.f);
            if (row < nrows) a = *(const float4*)(A + (long)row * K + kc + q * 4);
            if (RELU) {
                a.x = fmaxf(a.x, 0.f); a.y = fmaxf(a.y, 0.f);
                a.z = fmaxf(a.z, 0.f); a.w = fmaxf(a.w, 0.f);
            }
            sA[r][q * 4 + 0] = a.x; sA[r][q * 4 + 1] = a.y;
            sA[r][q * 4 + 2] = a.z; sA[r][q * 4 + 3] = a.w;
        }
        __syncthreads();

        #pragma unroll
        for (int k8 = 0; k8 < 4; ++k8) {
            int kk = k8 * 8;
            float av0 = sA[m0 + rg    ][kk + cg    ];
            float av1 = sA[m0 + rg + 8][kk + cg    ];
            float av2 = sA[m0 + rg    ][kk + cg + 4];
            float av3 = sA[m0 + rg + 8][kk + cg + 4];
            unsigned ab0 = f2tf(av0), ab1 = f2tf(av1), ab2 = f2tf(av2), ab3 = f2tf(av3);
            unsigned as0 = __float_as_uint(av0 - __uint_as_float(ab0));
            unsigned as1 = __float_as_uint(av1 - __uint_as_float(ab1));
            unsigned as2 = __float_as_uint(av2 - __uint_as_float(ab2));
            unsigned as3 = __float_as_uint(av3 - __uint_as_float(ab3));
            #pragma unroll
            for (int nt = 0; nt < 8; ++nt) {
                int n0 = nt * 8;
                float bv0 = sW[kc + kk + cg    ][n0 + rg];
                float bv1 = sW[kc + kk + cg + 4][n0 + rg];
                unsigned bb0 = f2tf(bv0), bb1 = f2tf(bv1);
                unsigned bs0 = __float_as_uint(bv0 - __uint_as_float(bb0));
                unsigned bs1 = __float_as_uint(bv1 - __uint_as_float(bb1));
                mma_tf32(d[nt], ab0, ab1, ab2, ab3, bb0, bb1);   // big*big
                mma_tf32(d[nt], ab0, ab1, ab2, ab3, bs0, bs1);   // big*small
                mma_tf32(d[nt], as0, as1, as2, as3, bb0, bb1);   // small*big
            }
        }
    }

    // epilogue: bias + store
    int r0 = row0 + m0 + rg;
    int r1 = r0 + 8;
    #pragma unroll
    for (int nt = 0; nt < 8; ++nt) {
        int n = nt * 8 + cg * 2;
        float b0 = bias[n], b1 = bias[n + 1];
        if (r0 < nrows) {
            float2 o = make_float2(d[nt][0] + b0, d[nt][1] + b1);
            *(float2*)(C + (long)r0 * 64 + n) = o;
        }
        if (r1 < nrows) {
            float2 o = make_float2(d[nt][2] + b0, d[nt][3] + b1);
            *(float2*)(C + (long)r1 * 64 + n) = o;
        }
    }
}

// ---------------- driver --------------------------------------------------------
extern "C" void kernel_launch(void* const* d_in, const int* in_sizes, int n_in,
                              void* d_out, int out_size) {
    const float* feat = (const float*)d_in[0];
    const float* Wb   = (const float*)d_in[1];
    const float* bb   = (const float*)d_in[2];
    const float* Wa   = (const float*)d_in[3];
    const float* ba   = (const float*)d_in[4];
    const int*   src  = (const int*)d_in[5];
    const int*   dst  = (const int*)d_in[6];
    float*       out  = (float*)d_out;
    int E = in_sizes[5];
    if (E > EE) E = EE;

    const int TPB    = 256;
    const int gN     = (NN + TPB - 1) / TPB;
    const int gE     = (E + TPB - 1) / TPB;
    const int gE4    = ((E + 3) / 4 + TPB - 1) / TPB;
    const int gE2    = ((E + 1) / 2 + TPB - 1) / TPB;
    const int gWarp  = (NN * 32 + TPB - 1) / TPB;   // warp per node
    const int gGemm  = (NN + 127) / 128;

    // CSR build + scatter writes phase-1 edge coefs directly
    k_zero_cnt<<<gN, TPB>>>();
    k_count<<<gE4, TPB>>>(dst, E);
    k_scanF<<<NB_SCAN, 1024>>>();
    k_scatter<<<gE, TPB>>>(src, dst, E);

    // X = feat @ W_bef + b_bef  (tf32 tensor cores, 3xTF32)
    k_gemm_tc<IND, false><<<gGemm, TPB>>>(feat, Wb, bb, nullptr, NN, 0, 0);

    // 4 prop steps: X(0) -> Ya(1) -> Yb(2) -> Ya(1) -> Yb(2)
    k_prop<<<gWarp, TPB>>>(0, 1);
    k_prop<<<gWarp, TPB>>>(1, 2);
    k_prop<<<gWarp, TPB>>>(2, 1);
    k_prop<<<gWarp, TPB>>>(1, 2);

    // attention on current Y (buf 2) with fused node coefs, then edge coefs
    k_attn<<<gWarp, TPB>>>(2);
    k_coef2<<<gE2, TPB>>>(E);

    // 4 more prop steps: Yb(2) -> Ya(1) -> Yb(2) -> Ya(1) -> Yb(2)
    k_prop<<<gWarp, TPB>>>(2, 1);
    k_prop<<<gWarp, TPB>>>(1, 2);
    k_prop<<<gWarp, TPB>>>(2, 1);
    k_prop<<<gWarp, TPB>>>(1, 2);

    // out = relu(Y) @ W_aft + b_aft  (tf32 tensor cores, 3xTF32)
    k_gemm_tc<HIDD, true><<<gGemm, TPB>>>(nullptr, Wa, ba, out, NN, 2, 0);
}